// round 13
// baseline (speedup 1.0000x reference)
#include <cuda_runtime.h>
#include <cuda_bf16.h>
#include <cstdint>

#define N_NODES 100000
#define D 256
#define E_MAX 3200000

typedef unsigned long long ull;

// ---------------- device scratch (static, per allocation rules) ------------
__device__ int   g_cnt[N_NODES];
__device__ int   g_rowstart[N_NODES + 1];
__device__ int   g_cursor[N_NODES];
__device__ int2  g_edges[E_MAX];               // interleaved (col, val-bits)
__device__ int   g_blocksums[128];
// bf16 copy of ego for the gather (halves L2 gather traffic)
__device__ __nv_bfloat16 g_ego_bf[(size_t)N_NODES * D];
// bf16 hi/lo split of weights, K-major [n][k]  (W2: hi only)
__device__ __nv_bfloat16 g_w1hi[D * D];
__device__ __nv_bfloat16 g_w1lo[D * D];
__device__ __nv_bfloat16 g_w2hi[D * D];
// bf16 split of GEMM A-operands, produced by pull_spmm (a2: hi only)
__device__ __nv_bfloat16 g_a1hi[(size_t)N_NODES * D];
__device__ __nv_bfloat16 g_a1lo[(size_t)N_NODES * D];
__device__ __nv_bfloat16 g_a2hi[(size_t)N_NODES * D];

// ===========================================================================
// helpers
// ===========================================================================
__device__ __forceinline__ uint32_t smem_to_u32(const void* p) {
    uint32_t a;
    asm("{ .reg .u64 t; cvta.to.shared.u64 t, %1; cvt.u32.u64 %0, t; }"
        : "=r"(a) : "l"(p));
    return a;
}
__device__ __forceinline__ void ldm_x4(uint32_t* r, uint32_t addr) {
    asm volatile("ldmatrix.sync.aligned.m8n8.x4.shared.b16 {%0,%1,%2,%3}, [%4];"
                 : "=r"(r[0]), "=r"(r[1]), "=r"(r[2]), "=r"(r[3]) : "r"(addr));
}
__device__ __forceinline__ void ldm_x2(uint32_t* r, uint32_t addr) {
    asm volatile("ldmatrix.sync.aligned.m8n8.x2.shared.b16 {%0,%1}, [%2];"
                 : "=r"(r[0]), "=r"(r[1]) : "r"(addr));
}
__device__ __forceinline__ void mma_bf16(float* d, const uint32_t* a, const uint32_t* b) {
    asm volatile("mma.sync.aligned.m16n8k16.row.col.f32.bf16.bf16.f32 "
                 "{%0,%1,%2,%3}, {%4,%5,%6,%7}, {%8,%9}, {%0,%1,%2,%3};"
                 : "+f"(d[0]), "+f"(d[1]), "+f"(d[2]), "+f"(d[3])
                 : "r"(a[0]), "r"(a[1]), "r"(a[2]), "r"(a[3]),
                   "r"(b[0]), "r"(b[1]));
}
__device__ __forceinline__ float lrelu(float x) { return x > 0.f ? x : 0.01f * x; }

// cp.async 16B with runtime src-size (0 -> zero-fill)
__device__ __forceinline__ void cp_async16(uint32_t dst, const void* src, int sz) {
    asm volatile("cp.async.cg.shared.global [%0], [%1], 16, %2;"
                 :: "r"(dst), "l"(src), "r"(sz) : "memory");
}
#define CP_COMMIT() asm volatile("cp.async.commit_group;" ::: "memory")
#define CP_WAIT1()  asm volatile("cp.async.wait_group 1;" ::: "memory")
#define CP_WAIT0()  asm volatile("cp.async.wait_group 0;" ::: "memory")

// pack 4 floats -> 4 bf16 (rn) in one 64-bit word
__device__ __forceinline__ ull pack4(float a, float b, float c, float d) {
    unsigned short u0 = __bfloat16_as_ushort(__float2bfloat16(a));
    unsigned short u1 = __bfloat16_as_ushort(__float2bfloat16(b));
    unsigned short u2 = __bfloat16_as_ushort(__float2bfloat16(c));
    unsigned short u3 = __bfloat16_as_ushort(__float2bfloat16(d));
    return (ull)u0 | ((ull)u1 << 16) | ((ull)u2 << 32) | ((ull)u3 << 48);
}
// exact bf16x2 -> 2 floats (shift / mask)
__device__ __forceinline__ float bf_lo(uint32_t u) { return __uint_as_float(u << 16); }
__device__ __forceinline__ float bf_hi(uint32_t u) { return __uint_as_float(u & 0xffff0000u); }

// ===========================================================================
// Fused prep: ego->bf16 copy  +  W split  +  zero counters  (disjoint work)
// ===========================================================================
__global__ void prep_kernel(const float* __restrict__ ego,
                            const float* __restrict__ W1,
                            const float* __restrict__ W2) {
    int i = blockIdx.x * blockDim.x + threadIdx.x;

    size_t ei = (size_t)i * 8;
    float4 f0 = *reinterpret_cast<const float4*>(ego + ei);
    float4 f1 = *reinterpret_cast<const float4*>(ego + ei + 4);
    *reinterpret_cast<ull*>(g_ego_bf + ei)     = pack4(f0.x, f0.y, f0.z, f0.w);
    *reinterpret_cast<ull*>(g_ego_bf + ei + 4) = pack4(f1.x, f1.y, f1.z, f1.w);

    if (i < D * D) {
        float w1 = W1[i];
        __nv_bfloat16 h1 = __float2bfloat16(w1);
        g_w1hi[i] = h1;
        g_w1lo[i] = __float2bfloat16(w1 - __bfloat162float(h1));
        g_w2hi[i] = __float2bfloat16(W2[i]);
    }

    if (i < N_NODES) g_cnt[i] = 0;
}

// ===========================================================================
// CSR build: histogram -> scan(3 kernels) -> bucket scatter
// ===========================================================================
__global__ void hist_kernel(const int* __restrict__ rows, int E) {
    int e4 = (blockIdx.x * blockDim.x + threadIdx.x) * 4;
    if (e4 + 3 < E) {
        int4 r = *reinterpret_cast<const int4*>(rows + e4);
        atomicAdd(&g_cnt[r.x], 1);
        atomicAdd(&g_cnt[r.y], 1);
        atomicAdd(&g_cnt[r.z], 1);
        atomicAdd(&g_cnt[r.w], 1);
    } else {
        for (int e = e4; e < E; e++) atomicAdd(&g_cnt[rows[e]], 1);
    }
}

#define SCAN_B 1024
__global__ void scan1_kernel() {
    __shared__ int sm[SCAN_B];
    int t = threadIdx.x;
    int i = blockIdx.x * SCAN_B + t;
    int x = (i < N_NODES) ? g_cnt[i] : 0;
    int val = x;
    sm[t] = val;
    __syncthreads();
#pragma unroll
    for (int off = 1; off < SCAN_B; off <<= 1) {
        int y = (t >= off) ? sm[t - off] : 0;
        __syncthreads();
        val += y;
        sm[t] = val;
        __syncthreads();
    }
    if (i < N_NODES) g_rowstart[i] = val - x;
    if (t == SCAN_B - 1) g_blocksums[blockIdx.x] = val;
}

__global__ void scan2_kernel(int nblocks) {
    __shared__ int sm[128];
    int t = threadIdx.x;
    int x = (t < nblocks) ? g_blocksums[t] : 0;
    int val = x;
    sm[t] = val;
    __syncthreads();
#pragma unroll
    for (int off = 1; off < 128; off <<= 1) {
        int y = (t >= off) ? sm[t - off] : 0;
        __syncthreads();
        val += y;
        sm[t] = val;
        __syncthreads();
    }
    if (t < nblocks) g_blocksums[t] = val - x;
}

__global__ void scan3_kernel(int E) {
    int i = blockIdx.x * SCAN_B + threadIdx.x;
    if (i < N_NODES) {
        int v = g_rowstart[i] + g_blocksums[blockIdx.x];
        g_rowstart[i] = v;
        g_cursor[i]   = v;
    }
    if (i == 0) g_rowstart[N_NODES] = E;
}

__global__ void bucket_kernel(const int* __restrict__ rows,
                              const int* __restrict__ cols,
                              const float* __restrict__ vals, int E) {
    int e4 = (blockIdx.x * blockDim.x + threadIdx.x) * 4;
    if (e4 + 3 < E) {
        int4  r = *reinterpret_cast<const int4*>(rows + e4);
        int4  c = *reinterpret_cast<const int4*>(cols + e4);
        int4  v = *reinterpret_cast<const int4*>(
                      reinterpret_cast<const int*>(vals) + e4);
        int p0 = atomicAdd(&g_cursor[r.x], 1);
        int p1 = atomicAdd(&g_cursor[r.y], 1);
        int p2 = atomicAdd(&g_cursor[r.z], 1);
        int p3 = atomicAdd(&g_cursor[r.w], 1);
        g_edges[p0] = make_int2(c.x, v.x);
        g_edges[p1] = make_int2(c.y, v.y);
        g_edges[p2] = make_int2(c.z, v.z);
        g_edges[p3] = make_int2(c.w, v.w);
    } else {
        for (int e = e4; e < E; e++) {
            int p = atomicAdd(&g_cursor[rows[e]], 1);
            g_edges[p] = make_int2(cols[e], __float_as_int(vals[e]));
        }
    }
}

// ===========================================================================
// Pull SpMM (bf16 gather, fp32 accumulate) + A-operand producer.
// ===========================================================================
__global__ void pull_spmm_kernel(const float* __restrict__ ego) {
    int row = (int)((blockIdx.x * blockDim.x + threadIdx.x) >> 5);
    if (row >= N_NODES) return;
    int lane = threadIdx.x & 31;

    int s = g_rowstart[row];
    int e = g_rowstart[row + 1];

    float acc[8] = {};

    for (int base = s; base < e; base += 32) {
        int rem = e - base; if (rem > 32) rem = 32;
        int   c = 0;
        float v = 0.f;
        if (lane < rem) {
            int2 ev = g_edges[base + lane];
            c = ev.x;
            v = __int_as_float(ev.y);
        }
        for (int j = 0; j < rem; j++) {
            int   cj = __shfl_sync(0xffffffffu, c, j);
            float vj = __shfl_sync(0xffffffffu, v, j);
            uint4 u = __ldg(reinterpret_cast<const uint4*>(
                          g_ego_bf + (size_t)cj * D + lane * 8));
            acc[0] = fmaf(bf_lo(u.x), vj, acc[0]);
            acc[1] = fmaf(bf_hi(u.x), vj, acc[1]);
            acc[2] = fmaf(bf_lo(u.y), vj, acc[2]);
            acc[3] = fmaf(bf_hi(u.y), vj, acc[3]);
            acc[4] = fmaf(bf_lo(u.z), vj, acc[4]);
            acc[5] = fmaf(bf_hi(u.z), vj, acc[5]);
            acc[6] = fmaf(bf_lo(u.w), vj, acc[6]);
            acc[7] = fmaf(bf_hi(u.w), vj, acc[7]);
        }
    }

    const float* erow = ego + (size_t)row * D + lane * 8;
    float4 e0 = __ldg(reinterpret_cast<const float4*>(erow));
    float4 e1 = __ldg(reinterpret_cast<const float4*>(erow + 4));
    float ev[8] = {e0.x, e0.y, e0.z, e0.w, e1.x, e1.y, e1.z, e1.w};

    float a1[8], a2[8], h1[8];
#pragma unroll
    for (int q = 0; q < 8; q++) {
        a1[q] = ev[q] + acc[q];
        a2[q] = ev[q] * acc[q];
        h1[q] = __bfloat162float(__float2bfloat16(a1[q]));
    }
    size_t off = (size_t)row * D + lane * 8;
    *reinterpret_cast<ull*>(g_a1hi + off)     = pack4(h1[0], h1[1], h1[2], h1[3]);
    *reinterpret_cast<ull*>(g_a1hi + off + 4) = pack4(h1[4], h1[5], h1[6], h1[7]);
    *reinterpret_cast<ull*>(g_a1lo + off) =
        pack4(a1[0] - h1[0], a1[1] - h1[1], a1[2] - h1[2], a1[3] - h1[3]);
    *reinterpret_cast<ull*>(g_a1lo + off + 4) =
        pack4(a1[4] - h1[4], a1[5] - h1[5], a1[6] - h1[6], a1[7] - h1[7]);
    *reinterpret_cast<ull*>(g_a2hi + off)     = pack4(a2[0], a2[1], a2[2], a2[3]);
    *reinterpret_cast<ull*>(g_a2hi + off + 4) = pack4(a2[4], a2[5], a2[6], a2[7]);
}

// ===========================================================================
// HMMA dual GEMM, A-resident version.
// grid 782x1. Per CTA: full-K A tiles (a1hi/a1lo/a2hi, 128x256 bf16 each,
// 196.6 KB) loaded into smem ONCE via cp.async; then 4 j-tiles x 8 k-chunks
// with W double-buffered. A smem rows are 512B with chunk^(row&7) swizzle
// -> conflict-free ldmatrix, no padding.
// 8 warps (4m x 2n), warp tile 32x32 per j-tile; acc stored+reset per j.
// ===========================================================================
#define ARS 512                      // A row stride bytes (256 bf16)
#define A_ONE (128 * ARS)            // 65536 per A buffer
#define OFF_A1H 0
#define OFF_A1L (OFF_A1H + A_ONE)
#define OFF_A2H (OFF_A1L + A_ONE)
#define W_BASE  (OFF_A2H + A_ONE)    // 196608
#define RSTRIDE 80
#define W_BUF (64 * RSTRIDE)         // 5120
#define W_STAGE (3 * W_BUF)          // 15360: W1H | W1L | W2H
#define SM_TOTAL (W_BASE + 2 * W_STAGE)   // 227328 bytes

__global__ void __launch_bounds__(256) gemm_mma_kernel(
    const float* __restrict__ b1, const float* __restrict__ b2,
    float* __restrict__ out) {

    extern __shared__ char smem[];
    uint32_t sb = smem_to_u32(smem);
    int t    = threadIdx.x;
    int lane = t & 31;
    int wid  = t >> 5;
    int row0 = blockIdx.x * 128;
    int mw   = (wid & 3) * 32;       // warp m origin
    int nw   = (wid >> 2) * 32;      // warp n origin within 64-wide j-tile

    // lane components for ldmatrix addressing
    int mloc = (lane & 7) + ((lane >> 3) & 1) * 8;
    int akh  = (lane >> 4) & 1;           // A k-half (16B) within k16
    int nloc = lane & 7;
    int bkb  = ((lane >> 3) & 1) * 16;    // W k-block byte offset (x2)

    // W loader indices
    int wn  = t >> 2;                // W row (0..63)
    int lkc = t & 3;                 // 16B chunk within 32-col slice

    // ---- issue A load (once): 3 bufs x 128 rows x 32 chunks ----
    {
#pragma unroll
        for (int it = 0; it < 16; it++) {
            int pos = it * 256 + t;          // 0..4095
            int r     = pos >> 5;            // 0..127
            int chunk = pos & 31;            // 16B chunk in row
            int gr  = row0 + r;
            int grc = (gr < N_NODES) ? gr : 0;
            int sz  = (gr < N_NODES) ? 16 : 0;
            uint32_t dst = (uint32_t)(r * ARS + (chunk ^ (r & 7)) * 16);
            size_t   src = (size_t)grc * D + chunk * 8;
            cp_async16(sb + OFF_A1H + dst, g_a1hi + src, sz);
            cp_async16(sb + OFF_A1L + dst, g_a1lo + src, sz);
            cp_async16(sb + OFF_A2H + dst, g_a2hi + src, sz);
        }
    }
    // ---- issue W(j=0,ch=0) into stage 0, same commit group as A ----
    {
        size_t src = (size_t)(0 + wn) * D + 0 + lkc * 8;
        uint32_t dst = (uint32_t)(wn * RSTRIDE + lkc * 16);
        uint32_t bo = sb + W_BASE;
        cp_async16(bo + 0 * W_BUF + dst, g_w1hi + src, 16);
        cp_async16(bo + 1 * W_BUF + dst, g_w1lo + src, 16);
        cp_async16(bo + 2 * W_BUF + dst, g_w2hi + src, 16);
    }
    CP_COMMIT();

    float acc1[2][4][4] = {}, acc2[2][4][4] = {};

    for (int j = 0; j < 4; j++) {
        for (int ch = 0; ch < 8; ch++) {
            int it  = j * 8 + ch;
            int nxt = it + 1;
            if (nxt < 32) {
                // prefetch W for next (j,ch) into the other stage
                int nj = nxt >> 3, nch = nxt & 7;
                size_t src = (size_t)(nj * 64 + wn) * D + nch * 32 + lkc * 8;
                uint32_t dst = (uint32_t)(wn * RSTRIDE + lkc * 16);
                uint32_t bo = sb + W_BASE + (nxt & 1) * W_STAGE;
                cp_async16(bo + 0 * W_BUF + dst, g_w1hi + src, 16);
                cp_async16(bo + 1 * W_BUF + dst, g_w1lo + src, 16);
                cp_async16(bo + 2 * W_BUF + dst, g_w2hi + src, 16);
                CP_COMMIT();
                CP_WAIT1();
            } else {
                CP_WAIT0();
            }
            __syncthreads();

            uint32_t wo = sb + W_BASE + (it & 1) * W_STAGE;

            // ---- MMA: 2 k-steps of 16 within this 32-col chunk ----
#pragma unroll
            for (int ks = 0; ks < 2; ks++) {
                int kb = ks * 32;             // W byte offset within row

                uint32_t af1[2][2][4], af2[2][4];
                uint32_t bf1[2][4][2], bf2[4][2];
#pragma unroll
                for (int ms = 0; ms < 2; ms++) {
                    int ar = mw + ms * 16 + mloc;
                    int chunk = ch * 4 + ks * 2 + akh;          // global 16B chunk
                    uint32_t arow = (uint32_t)(ar * ARS + (chunk ^ (ar & 7)) * 16);
                    ldm_x4(af1[0][ms], sb + OFF_A1H + arow);
                    ldm_x4(af1[1][ms], sb + OFF_A1L + arow);
                    ldm_x4(af2[ms],    sb + OFF_A2H + arow);
                }
#pragma unroll
                for (int ns = 0; ns < 4; ns++) {
                    uint32_t brow = (uint32_t)((nw + ns * 8 + nloc) * RSTRIDE + kb + bkb);
                    ldm_x2(bf1[0][ns], wo + 0 * W_BUF + brow);
                    ldm_x2(bf1[1][ns], wo + 1 * W_BUF + brow);
                    ldm_x2(bf2[ns],    wo + 2 * W_BUF + brow);
                }
#pragma unroll
                for (int ms = 0; ms < 2; ms++) {
#pragma unroll
                    for (int ns = 0; ns < 4; ns++) {
                        // path 1: hi*hi + hi*lo + lo*hi (compensated)
                        mma_bf16(acc1[ms][ns], af1[0][ms], bf1[0][ns]);
                        mma_bf16(acc1[ms][ns], af1[0][ms], bf1[1][ns]);
                        mma_bf16(acc1[ms][ns], af1[1][ms], bf1[0][ns]);
                        // path 2: hi*hi only
                        mma_bf16(acc2[ms][ns], af2[ms], bf2[ns]);
                    }
                }
            }
            __syncthreads();   // W stage (it&1) free for reuse at it+2
        }

        // ---- epilogue for this j-tile, then reset accumulators ----
        int j0 = j * 64;
        float2 b1v[4], b2v[4];
#pragma unroll
        for (int ns = 0; ns < 4; ns++) {
            int ng = j0 + nw + ns * 8 + 2 * (lane & 3);
            b1v[ns] = *reinterpret_cast<const float2*>(b1 + ng);
            b2v[ns] = *reinterpret_cast<const float2*>(b2 + ng);
        }
#pragma unroll
        for (int ms = 0; ms < 2; ms++) {
#pragma unroll
            for (int h = 0; h < 2; h++) {
                int gm = row0 + mw + ms * 16 + (lane >> 2) + h * 8;
                if (gm < N_NODES) {
#pragma unroll
                    for (int ns = 0; ns < 4; ns++) {
                        int ng = j0 + nw + ns * 8 + 2 * (lane & 3);
                        float2 o;
                        o.x = lrelu(acc1[ms][ns][h * 2 + 0] + b1v[ns].x) +
                              lrelu(acc2[ms][ns][h * 2 + 0] + b2v[ns].x);
                        o.y = lrelu(acc1[ms][ns][h * 2 + 1] + b1v[ns].y) +
                              lrelu(acc2[ms][ns][h * 2 + 1] + b2v[ns].y);
                        *reinterpret_cast<float2*>(out + (size_t)gm * D + ng) = o;
                    }
                }
            }
        }
#pragma unroll
        for (int ms = 0; ms < 2; ms++)
#pragma unroll
            for (int ns = 0; ns < 4; ns++)
#pragma unroll
                for (int q = 0; q < 4; q++) {
                    acc1[ms][ns][q] = 0.f;
                    acc2[ms][ns][q] = 0.f;
                }
    }
}

// ===========================================================================
// Launch sequence (all graph-capturable, stream-ordered)
// ===========================================================================
extern "C" void kernel_launch(void* const* d_in, const int* in_sizes, int n_in,
                              void* d_out, int out_size) {
    const float* ego  = (const float*)d_in[0];
    const float* vals = (const float*)d_in[1];
    const float* W1   = (const float*)d_in[2];
    const float* b1   = (const float*)d_in[3];
    const float* W2   = (const float*)d_in[4];
    const float* b2   = (const float*)d_in[5];
    const int*   rows = (const int*)d_in[6];
    const int*   cols = (const int*)d_in[7];
    float*       out  = (float*)d_out;

    int E = in_sizes[1];
    int scan_blocks = (N_NODES + SCAN_B - 1) / SCAN_B;   // 98

    // fused prep: ego->bf16, W split, zero counters
    prep_kernel<<<(N_NODES * D / 8) / 256, 256>>>(ego, W1, W2);

    // CSR build
    hist_kernel<<<(E / 4 + 255) / 256, 256>>>(rows, E);
    scan1_kernel<<<scan_blocks, SCAN_B>>>();
    scan2_kernel<<<1, 128>>>(scan_blocks);
    scan3_kernel<<<scan_blocks, SCAN_B>>>(E);
    bucket_kernel<<<(E / 4 + 255) / 256, 256>>>(rows, cols, vals, E);

    // pull SpMM (bf16 gather) + A-operand split: one warp per row
    pull_spmm_kernel<<<(N_NODES * 32 + 255) / 256, 256>>>(ego);

    // HMMA dual GEMM, A-resident (grid 782x1)
    cudaFuncSetAttribute(gemm_mma_kernel,
                         cudaFuncAttributeMaxDynamicSharedMemorySize, SM_TOTAL);
    gemm_mma_kernel<<<(N_NODES + 127) / 128, 256, SM_TOTAL>>>(b1, b2, out);
}

// round 14
// speedup vs baseline: 1.0590x; 1.0590x over previous
#include <cuda_runtime.h>
#include <cuda_bf16.h>
#include <cstdint>

#define N_NODES 100000
#define D 256
#define E_MAX 3200000

typedef unsigned long long ull;

// ---------------- device scratch (static, per allocation rules) ------------
__device__ int   g_cnt[N_NODES];
__device__ int   g_rowstart[N_NODES + 1];
__device__ int   g_cursor[N_NODES];
__device__ int2  g_edges[E_MAX];               // interleaved (col, val-bits)
__device__ int   g_blocksums[128];
// bf16 copy of ego for the gather (halves L2 gather traffic)
__device__ __nv_bfloat16 g_ego_bf[(size_t)N_NODES * D];
// bf16 hi/lo split of weights, K-major [n][k]  (W2: hi only)
__device__ __nv_bfloat16 g_w1hi[D * D];
__device__ __nv_bfloat16 g_w1lo[D * D];
__device__ __nv_bfloat16 g_w2hi[D * D];
// bf16 split of GEMM A-operands, produced by pull_spmm (a2: hi only)
__device__ __nv_bfloat16 g_a1hi[(size_t)N_NODES * D];
__device__ __nv_bfloat16 g_a1lo[(size_t)N_NODES * D];
__device__ __nv_bfloat16 g_a2hi[(size_t)N_NODES * D];

// ===========================================================================
// helpers
// ===========================================================================
__device__ __forceinline__ uint32_t smem_to_u32(const void* p) {
    uint32_t a;
    asm("{ .reg .u64 t; cvta.to.shared.u64 t, %1; cvt.u32.u64 %0, t; }"
        : "=r"(a) : "l"(p));
    return a;
}
__device__ __forceinline__ void ldm_x4(uint32_t* r, uint32_t addr) {
    asm volatile("ldmatrix.sync.aligned.m8n8.x4.shared.b16 {%0,%1,%2,%3}, [%4];"
                 : "=r"(r[0]), "=r"(r[1]), "=r"(r[2]), "=r"(r[3]) : "r"(addr));
}
__device__ __forceinline__ void ldm_x2(uint32_t* r, uint32_t addr) {
    asm volatile("ldmatrix.sync.aligned.m8n8.x2.shared.b16 {%0,%1}, [%2];"
                 : "=r"(r[0]), "=r"(r[1]) : "r"(addr));
}
__device__ __forceinline__ void mma_bf16(float* d, const uint32_t* a, const uint32_t* b) {
    asm volatile("mma.sync.aligned.m16n8k16.row.col.f32.bf16.bf16.f32 "
                 "{%0,%1,%2,%3}, {%4,%5,%6,%7}, {%8,%9}, {%0,%1,%2,%3};"
                 : "+f"(d[0]), "+f"(d[1]), "+f"(d[2]), "+f"(d[3])
                 : "r"(a[0]), "r"(a[1]), "r"(a[2]), "r"(a[3]),
                   "r"(b[0]), "r"(b[1]));
}
__device__ __forceinline__ float lrelu(float x) { return x > 0.f ? x : 0.01f * x; }

// cp.async 16B with runtime src-size (0 -> zero-fill)
__device__ __forceinline__ void cp_async16(uint32_t dst, const void* src, int sz) {
    asm volatile("cp.async.cg.shared.global [%0], [%1], 16, %2;"
                 :: "r"(dst), "l"(src), "r"(sz) : "memory");
}
#define CP_COMMIT() asm volatile("cp.async.commit_group;" ::: "memory")
#define CP_WAIT1()  asm volatile("cp.async.wait_group 1;" ::: "memory")
#define CP_WAIT0()  asm volatile("cp.async.wait_group 0;" ::: "memory")

// pack 4 floats -> 4 bf16 (rn) in one 64-bit word
__device__ __forceinline__ ull pack4(float a, float b, float c, float d) {
    unsigned short u0 = __bfloat16_as_ushort(__float2bfloat16(a));
    unsigned short u1 = __bfloat16_as_ushort(__float2bfloat16(b));
    unsigned short u2 = __bfloat16_as_ushort(__float2bfloat16(c));
    unsigned short u3 = __bfloat16_as_ushort(__float2bfloat16(d));
    return (ull)u0 | ((ull)u1 << 16) | ((ull)u2 << 32) | ((ull)u3 << 48);
}
// exact bf16x2 -> 2 floats (shift / mask)
__device__ __forceinline__ float bf_lo(uint32_t u) { return __uint_as_float(u << 16); }
__device__ __forceinline__ float bf_hi(uint32_t u) { return __uint_as_float(u & 0xffff0000u); }

// ===========================================================================
// Fused prep: ego->bf16 copy  +  W split  +  zero counters  (disjoint work)
// ===========================================================================
__global__ void prep_kernel(const float* __restrict__ ego,
                            const float* __restrict__ W1,
                            const float* __restrict__ W2) {
    int i = blockIdx.x * blockDim.x + threadIdx.x;

    size_t ei = (size_t)i * 8;
    float4 f0 = *reinterpret_cast<const float4*>(ego + ei);
    float4 f1 = *reinterpret_cast<const float4*>(ego + ei + 4);
    *reinterpret_cast<ull*>(g_ego_bf + ei)     = pack4(f0.x, f0.y, f0.z, f0.w);
    *reinterpret_cast<ull*>(g_ego_bf + ei + 4) = pack4(f1.x, f1.y, f1.z, f1.w);

    if (i < D * D) {
        float w1 = W1[i];
        __nv_bfloat16 h1 = __float2bfloat16(w1);
        g_w1hi[i] = h1;
        g_w1lo[i] = __float2bfloat16(w1 - __bfloat162float(h1));
        g_w2hi[i] = __float2bfloat16(W2[i]);
    }

    if (i < N_NODES) g_cnt[i] = 0;
}

// ===========================================================================
// CSR build: histogram -> scan(3 kernels) -> bucket scatter
// ===========================================================================
__global__ void hist_kernel(const int* __restrict__ rows, int E) {
    int e4 = (blockIdx.x * blockDim.x + threadIdx.x) * 4;
    if (e4 + 3 < E) {
        int4 r = *reinterpret_cast<const int4*>(rows + e4);
        atomicAdd(&g_cnt[r.x], 1);
        atomicAdd(&g_cnt[r.y], 1);
        atomicAdd(&g_cnt[r.z], 1);
        atomicAdd(&g_cnt[r.w], 1);
    } else {
        for (int e = e4; e < E; e++) atomicAdd(&g_cnt[rows[e]], 1);
    }
}

#define SCAN_B 1024
__global__ void scan1_kernel() {
    __shared__ int sm[SCAN_B];
    int t = threadIdx.x;
    int i = blockIdx.x * SCAN_B + t;
    int x = (i < N_NODES) ? g_cnt[i] : 0;
    int val = x;
    sm[t] = val;
    __syncthreads();
#pragma unroll
    for (int off = 1; off < SCAN_B; off <<= 1) {
        int y = (t >= off) ? sm[t - off] : 0;
        __syncthreads();
        val += y;
        sm[t] = val;
        __syncthreads();
    }
    if (i < N_NODES) g_rowstart[i] = val - x;
    if (t == SCAN_B - 1) g_blocksums[blockIdx.x] = val;
}

__global__ void scan2_kernel(int nblocks) {
    __shared__ int sm[128];
    int t = threadIdx.x;
    int x = (t < nblocks) ? g_blocksums[t] : 0;
    int val = x;
    sm[t] = val;
    __syncthreads();
#pragma unroll
    for (int off = 1; off < 128; off <<= 1) {
        int y = (t >= off) ? sm[t - off] : 0;
        __syncthreads();
        val += y;
        sm[t] = val;
        __syncthreads();
    }
    if (t < nblocks) g_blocksums[t] = val - x;
}

__global__ void scan3_kernel(int E) {
    int i = blockIdx.x * SCAN_B + threadIdx.x;
    if (i < N_NODES) {
        int v = g_rowstart[i] + g_blocksums[blockIdx.x];
        g_rowstart[i] = v;
        g_cursor[i]   = v;
    }
    if (i == 0) g_rowstart[N_NODES] = E;
}

__global__ void bucket_kernel(const int* __restrict__ rows,
                              const int* __restrict__ cols,
                              const float* __restrict__ vals, int E) {
    int e4 = (blockIdx.x * blockDim.x + threadIdx.x) * 4;
    if (e4 + 3 < E) {
        int4  r = *reinterpret_cast<const int4*>(rows + e4);
        int4  c = *reinterpret_cast<const int4*>(cols + e4);
        int4  v = *reinterpret_cast<const int4*>(
                      reinterpret_cast<const int*>(vals) + e4);
        int p0 = atomicAdd(&g_cursor[r.x], 1);
        int p1 = atomicAdd(&g_cursor[r.y], 1);
        int p2 = atomicAdd(&g_cursor[r.z], 1);
        int p3 = atomicAdd(&g_cursor[r.w], 1);
        g_edges[p0] = make_int2(c.x, v.x);
        g_edges[p1] = make_int2(c.y, v.y);
        g_edges[p2] = make_int2(c.z, v.z);
        g_edges[p3] = make_int2(c.w, v.w);
    } else {
        for (int e = e4; e < E; e++) {
            int p = atomicAdd(&g_cursor[rows[e]], 1);
            g_edges[p] = make_int2(cols[e], __float_as_int(vals[e]));
        }
    }
}

// ===========================================================================
// Pull SpMM (bf16 gather, fp32 accumulate) + A-operand producer.
// ===========================================================================
__global__ void pull_spmm_kernel(const float* __restrict__ ego) {
    int row = (int)((blockIdx.x * blockDim.x + threadIdx.x) >> 5);
    if (row >= N_NODES) return;
    int lane = threadIdx.x & 31;

    int s = g_rowstart[row];
    int e = g_rowstart[row + 1];

    float acc[8] = {};

    for (int base = s; base < e; base += 32) {
        int rem = e - base; if (rem > 32) rem = 32;
        int   c = 0;
        float v = 0.f;
        if (lane < rem) {
            int2 ev = g_edges[base + lane];
            c = ev.x;
            v = __int_as_float(ev.y);
        }
        for (int j = 0; j < rem; j++) {
            int   cj = __shfl_sync(0xffffffffu, c, j);
            float vj = __shfl_sync(0xffffffffu, v, j);
            uint4 u = __ldg(reinterpret_cast<const uint4*>(
                          g_ego_bf + (size_t)cj * D + lane * 8));
            acc[0] = fmaf(bf_lo(u.x), vj, acc[0]);
            acc[1] = fmaf(bf_hi(u.x), vj, acc[1]);
            acc[2] = fmaf(bf_lo(u.y), vj, acc[2]);
            acc[3] = fmaf(bf_hi(u.y), vj, acc[3]);
            acc[4] = fmaf(bf_lo(u.z), vj, acc[4]);
            acc[5] = fmaf(bf_hi(u.z), vj, acc[5]);
            acc[6] = fmaf(bf_lo(u.w), vj, acc[6]);
            acc[7] = fmaf(bf_hi(u.w), vj, acc[7]);
        }
    }

    const float* erow = ego + (size_t)row * D + lane * 8;
    float4 e0 = __ldg(reinterpret_cast<const float4*>(erow));
    float4 e1 = __ldg(reinterpret_cast<const float4*>(erow + 4));
    float ev[8] = {e0.x, e0.y, e0.z, e0.w, e1.x, e1.y, e1.z, e1.w};

    float a1[8], a2[8], h1[8];
#pragma unroll
    for (int q = 0; q < 8; q++) {
        a1[q] = ev[q] + acc[q];
        a2[q] = ev[q] * acc[q];
        h1[q] = __bfloat162float(__float2bfloat16(a1[q]));
    }
    size_t off = (size_t)row * D + lane * 8;
    *reinterpret_cast<ull*>(g_a1hi + off)     = pack4(h1[0], h1[1], h1[2], h1[3]);
    *reinterpret_cast<ull*>(g_a1hi + off + 4) = pack4(h1[4], h1[5], h1[6], h1[7]);
    *reinterpret_cast<ull*>(g_a1lo + off) =
        pack4(a1[0] - h1[0], a1[1] - h1[1], a1[2] - h1[2], a1[3] - h1[3]);
    *reinterpret_cast<ull*>(g_a1lo + off + 4) =
        pack4(a1[4] - h1[4], a1[5] - h1[5], a1[6] - h1[6], a1[7] - h1[7]);
    *reinterpret_cast<ull*>(g_a2hi + off)     = pack4(a2[0], a2[1], a2[2], a2[3]);
    *reinterpret_cast<ull*>(g_a2hi + off + 4) = pack4(a2[4], a2[5], a2[6], a2[7]);
}

// ===========================================================================
// HMMA dual GEMM (R10 tiling: 128m x 64n, cp.async double-buffered).
// GRID SWAPPED: blockIdx.x = j-tile (fastest) so the 4 CTAs sharing one
// m-tile's A operands are launch-adjacent -> A read once from DRAM, then
// L2 hits for the 3 siblings (A total 153MB > L2, ordering is what matters).
// 8 warps (4m x 2n), warp tile 32x32, BK=32, 8 chunks.
// smem rows padded to 80B -> conflict-free ldmatrix.
// ===========================================================================
#define RSTRIDE 80
#define A_BUF (128 * RSTRIDE)       // 10240
#define W_BUF (64 * RSTRIDE)        // 5120
#define OFF_A1H 0
#define OFF_A1L (OFF_A1H + A_BUF)
#define OFF_A2H (OFF_A1L + A_BUF)
#define OFF_W1H (OFF_A2H + A_BUF)
#define OFF_W1L (OFF_W1H + W_BUF)
#define OFF_W2H (OFF_W1L + W_BUF)
#define SM_BUF  (OFF_W2H + W_BUF)   // 46080 per stage
#define SM_TOTAL (2 * SM_BUF)       // 92160 bytes

__global__ void __launch_bounds__(256) gemm_mma_kernel(
    const float* __restrict__ b1, const float* __restrict__ b2,
    float* __restrict__ out) {

    extern __shared__ char smem[];
    uint32_t sb = smem_to_u32(smem);
    int t    = threadIdx.x;
    int lane = t & 31;
    int wid  = t >> 5;
    int row0 = blockIdx.y * 128;     // m-tile (slow dim)
    int j0   = blockIdx.x * 64;      // j-tile (fast dim -> A reuse in L2)
    int mw   = (wid & 3) * 32;       // warp m origin in tile
    int nw   = (wid >> 2) * 32;      // warp n origin in tile

    // lane components for ldmatrix addressing
    int mloc = (lane & 7) + ((lane >> 3) & 1) * 8;
    int akb  = ((lane >> 4) & 1) * 16;    // k-block byte offset (A, x4)
    int nloc = lane & 7;
    int bkb  = ((lane >> 3) & 1) * 16;    // k-block byte offset (B, x2)

    // precomputed loader indices
    int lr0 = t >> 2;                // A row for s=0 (0..63)
    int lkc = t & 3;                 // 16B chunk
    int wn  = t >> 2;                // W row (0..63)

    // issue cp.async loads for chunk ch into buffer buf
    auto issue = [&](int ch, int buf) {
        int k0 = ch * 32;
        uint32_t bo = sb + buf * SM_BUF;
#pragma unroll
        for (int s = 0; s < 2; s++) {
            int r  = lr0 + s * 64;
            int gr = row0 + r;
            int grc = (gr < N_NODES) ? gr : 0;      // clamp (zero-filled anyway)
            int sz  = (gr < N_NODES) ? 16 : 0;
            uint32_t dst = (uint32_t)(r * RSTRIDE + lkc * 16);
            size_t src = (size_t)grc * D + k0 + lkc * 8;
            cp_async16(bo + OFF_A1H + dst, g_a1hi + src, sz);
            cp_async16(bo + OFF_A1L + dst, g_a1lo + src, sz);
            cp_async16(bo + OFF_A2H + dst, g_a2hi + src, sz);
        }
        {
            size_t src = (size_t)(j0 + wn) * D + k0 + lkc * 8;
            uint32_t dst = (uint32_t)(wn * RSTRIDE + lkc * 16);
            cp_async16(bo + OFF_W1H + dst, g_w1hi + src, 16);
            cp_async16(bo + OFF_W1L + dst, g_w1lo + src, 16);
            cp_async16(bo + OFF_W2H + dst, g_w2hi + src, 16);
        }
    };

    float acc1[2][4][4] = {}, acc2[2][4][4] = {};

    issue(0, 0);
    CP_COMMIT();

    for (int ch = 0; ch < 8; ch++) {
        if (ch < 7) {
            issue(ch + 1, (ch + 1) & 1);
            CP_COMMIT();
            CP_WAIT1();                 // chunk ch landed; ch+1 in flight
        } else {
            CP_WAIT0();
        }
        __syncthreads();

        uint32_t bo = sb + (ch & 1) * SM_BUF;

        // ---- MMA: 2 k-steps of 16 ----
#pragma unroll
        for (int ks = 0; ks < 2; ks++) {
            int kb = ks * 32;

            uint32_t af1[2][2][4], af2[2][4];
            uint32_t bf1[2][4][2], bf2[4][2];
#pragma unroll
            for (int ms = 0; ms < 2; ms++) {
                uint32_t arow = (uint32_t)((mw + ms * 16 + mloc) * RSTRIDE + kb + akb);
                ldm_x4(af1[0][ms], bo + OFF_A1H + arow);
                ldm_x4(af1[1][ms], bo + OFF_A1L + arow);
                ldm_x4(af2[ms],    bo + OFF_A2H + arow);
            }
#pragma unroll
            for (int ns = 0; ns < 4; ns++) {
                uint32_t brow = (uint32_t)((nw + ns * 8 + nloc) * RSTRIDE + kb + bkb);
                ldm_x2(bf1[0][ns], bo + OFF_W1H + brow);
                ldm_x2(bf1[1][ns], bo + OFF_W1L + brow);
                ldm_x2(bf2[ns],    bo + OFF_W2H + brow);
            }
#pragma unroll
            for (int ms = 0; ms < 2; ms++) {
#pragma unroll
                for (int ns = 0; ns < 4; ns++) {
                    // path 1: hi*hi + hi*lo + lo*hi (compensated)
                    mma_bf16(acc1[ms][ns], af1[0][ms], bf1[0][ns]);
                    mma_bf16(acc1[ms][ns], af1[0][ms], bf1[1][ns]);
                    mma_bf16(acc1[ms][ns], af1[1][ms], bf1[0][ns]);
                    // path 2: hi*hi only (bi path ~100x smaller magnitude)
                    mma_bf16(acc2[ms][ns], af2[ms], bf2[ns]);
                }
            }
        }
        __syncthreads();   // buffer (ch&1) free for reuse at ch+2
    }

    // ---- epilogue ----
    float2 b1v[4], b2v[4];
#pragma unroll
    for (int ns = 0; ns < 4; ns++) {
        int ng = j0 + nw + ns * 8 + 2 * (lane & 3);
        b1v[ns] = *reinterpret_cast<const float2*>(b1 + ng);
        b2v[ns] = *reinterpret_cast<const float2*>(b2 + ng);
    }
#pragma unroll
    for (int ms = 0; ms < 2; ms++) {
#pragma unroll
        for (int h = 0; h < 2; h++) {
            int gm = row0 + mw + ms * 16 + (lane >> 2) + h * 8;
            if (gm < N_NODES) {
#pragma unroll
                for (int ns = 0; ns < 4; ns++) {
                    int ng = j0 + nw + ns * 8 + 2 * (lane & 3);
                    float2 o;
                    o.x = lrelu(acc1[ms][ns][h * 2 + 0] + b1v[ns].x) +
                          lrelu(acc2[ms][ns][h * 2 + 0] + b2v[ns].x);
                    o.y = lrelu(acc1[ms][ns][h * 2 + 1] + b1v[ns].y) +
                          lrelu(acc2[ms][ns][h * 2 + 1] + b2v[ns].y);
                    *reinterpret_cast<float2*>(out + (size_t)gm * D + ng) = o;
                }
            }
        }
    }
}

// ===========================================================================
// Launch sequence (all graph-capturable, stream-ordered)
// ===========================================================================
extern "C" void kernel_launch(void* const* d_in, const int* in_sizes, int n_in,
                              void* d_out, int out_size) {
    const float* ego  = (const float*)d_in[0];
    const float* vals = (const float*)d_in[1];
    const float* W1   = (const float*)d_in[2];
    const float* b1   = (const float*)d_in[3];
    const float* W2   = (const float*)d_in[4];
    const float* b2   = (const float*)d_in[5];
    const int*   rows = (const int*)d_in[6];
    const int*   cols = (const int*)d_in[7];
    float*       out  = (float*)d_out;

    int E = in_sizes[1];
    int scan_blocks = (N_NODES + SCAN_B - 1) / SCAN_B;   // 98

    // fused prep: ego->bf16, W split, zero counters
    prep_kernel<<<(N_NODES * D / 8) / 256, 256>>>(ego, W1, W2);

    // CSR build
    hist_kernel<<<(E / 4 + 255) / 256, 256>>>(rows, E);
    scan1_kernel<<<scan_blocks, SCAN_B>>>();
    scan2_kernel<<<1, 128>>>(scan_blocks);
    scan3_kernel<<<scan_blocks, SCAN_B>>>(E);
    bucket_kernel<<<(E / 4 + 255) / 256, 256>>>(rows, cols, vals, E);

    // pull SpMM (bf16 gather) + A-operand split: one warp per row
    pull_spmm_kernel<<<(N_NODES * 32 + 255) / 256, 256>>>(ego);

    // HMMA dual GEMM + fused epilogue (j-fastest grid for A L2 reuse)
    cudaFuncSetAttribute(gemm_mma_kernel,
                         cudaFuncAttributeMaxDynamicSharedMemorySize, SM_TOTAL);
    dim3 grid(D / 64, (N_NODES + 127) / 128);   // 4 x 782, j fastest
    gemm_mma_kernel<<<grid, 256, SM_TOTAL>>>(b1, b2, out);
}